// round 12
// baseline (speedup 1.0000x reference)
#include <cuda_runtime.h>
#include <cuda_bf16.h>
#include <math.h>
#include <stdint.h>

#define SS 128
#define BB 128
#define VV 10000
#define HH 512
#define EE 512
#define KDIM 512

// ---------------- scratch (device globals: no allocations allowed) ----------
__device__ float g_P[VV * HH];          // scale * emb @ W0_x^T
__device__ unsigned int g_sync4[128];   // 4 batch-group barriers, 128B apart
// hidden state as bf16 hi/lo ping-pong (MMA operands)
__device__ __nv_bfloat16 g_h0bh[2][BB * HH], g_h0bl[2][BB * HH];
__device__ __nv_bfloat16 g_h1bh[2][BB * HH], g_h1bl[2][BB * HH];
// bf16 hi/lo split operands for tensor GEMMs
__device__ __nv_bfloat16 g_Thi[SS * BB * HH];
__device__ __nv_bfloat16 g_Tlo[SS * BB * HH];
__device__ __nv_bfloat16 g_Whi[VV * HH];
__device__ __nv_bfloat16 g_Wlo[VV * HH];
__device__ __nv_bfloat16 g_Ehi[VV * EE];
__device__ __nv_bfloat16 g_Elo[VV * EE];
__device__ __nv_bfloat16 g_Xhi[HH * EE];
__device__ __nv_bfloat16 g_Xlo[HH * EE];

// ============================ helpers ========================================
__device__ __forceinline__ uint32_t smem_u32(const void* p) {
    uint32_t a;
    asm("{ .reg .u64 t; cvta.to.shared.u64 t, %1; cvt.u32.u64 %0, t; }"
        : "=r"(a) : "l"(p));
    return a;
}

__device__ __forceinline__ void ldm_x4(uint32_t addr, uint32_t r[4]) {
    asm volatile("ldmatrix.sync.aligned.m8n8.x4.shared.b16 {%0,%1,%2,%3}, [%4];"
                 : "=r"(r[0]), "=r"(r[1]), "=r"(r[2]), "=r"(r[3]) : "r"(addr));
}

__device__ __forceinline__ void mma_bf16(float c[4], const uint32_t a[4],
                                         uint32_t b0, uint32_t b1) {
    asm volatile(
        "mma.sync.aligned.m16n8k16.row.col.f32.bf16.bf16.f32 "
        "{%0,%1,%2,%3}, {%4,%5,%6,%7}, {%8,%9}, {%0,%1,%2,%3};"
        : "+f"(c[0]), "+f"(c[1]), "+f"(c[2]), "+f"(c[3])
        : "r"(a[0]), "r"(a[1]), "r"(a[2]), "r"(a[3]), "r"(b0), "r"(b1));
}

// =================== bf16-split HMMA GEMM, 2-stage, 2 CTAs/SM ================
#define BK 32
#define ROWB 80
#define TILE_SB (128 * ROWB)
#define STAGE_SB (4 * TILE_SB)
#define GEMM_SMEM (2 * STAGE_SB)       // 81920 -> two CTAs co-resident per SM
#define KT_N (KDIM / BK)               // 16

__global__ __launch_bounds__(256, 2)
void gemm_hmma(const __nv_bfloat16* __restrict__ Ahi,
               const __nv_bfloat16* __restrict__ Alo,
               const __nv_bfloat16* __restrict__ Bhi,
               const __nv_bfloat16* __restrict__ Blo,
               int M, int N, float* __restrict__ C, int ldc,
               const float* __restrict__ bias) {
    extern __shared__ char smem[];
    const uint32_t sb = smem_u32(smem);
    const int tid = threadIdx.x;
    const int wid = tid >> 5, lid = tid & 31;
    const int wm = wid & 3, wn = wid >> 2;
    const int nb = blockIdx.x, mb = blockIdx.y;

    const __nv_bfloat16* __restrict__ srcs[4] = {Ahi, Alo, Bhi, Blo};

    float acc[2][8][4];
#pragma unroll
    for (int i = 0; i < 2; i++)
#pragma unroll
        for (int j = 0; j < 8; j++)
#pragma unroll
            for (int q = 0; q < 4; q++) acc[i][j][q] = 0.0f;

    auto load_stage = [&](int st, int kt) {
#pragma unroll
        for (int t = 0; t < 4; t++) {
#pragma unroll
            for (int i = 0; i < 2; i++) {
                const int idx = tid + i * 256;
                const int row = idx >> 2, ch = idx & 3;
                const long long grow =
                    (t < 2) ? (long long)mb * 128 + row : (long long)nb * 128 + row;
                const bool ok = (t < 2) ? (grow < M) : (grow < N);
                const __nv_bfloat16* src = srcs[t] + grow * KDIM + kt * BK + ch * 8;
                const uint32_t dst = sb + st * STAGE_SB + t * TILE_SB + row * ROWB + ch * 16;
                const int sz = ok ? 16 : 0;
                asm volatile("cp.async.cg.shared.global [%0], [%1], 16, %2;"
                             :: "r"(dst), "l"(src), "r"(sz) : "memory");
            }
        }
        asm volatile("cp.async.commit_group;" ::: "memory");
    };

    const int lr = lid & 15;
    const int lc = lid >> 4;

    load_stage(0, 0);

    for (int kt = 0; kt < KT_N; kt++) {
        const int st = kt & 1;
        if (kt + 1 < KT_N) {
            load_stage(st ^ 1, kt + 1);
            asm volatile("cp.async.wait_group 1;" ::: "memory");
        } else {
            asm volatile("cp.async.wait_group 0;" ::: "memory");
        }
        __syncthreads();

        const uint32_t stg = sb + st * STAGE_SB;
        const uint32_t aBaseHi = stg + 0 * TILE_SB;
        const uint32_t aBaseLo = stg + 1 * TILE_SB;
        const uint32_t bBaseHi = stg + 2 * TILE_SB;
        const uint32_t bBaseLo = stg + 3 * TILE_SB;

#pragma unroll
        for (int k16 = 0; k16 < 2; k16++) {
            const uint32_t koff = k16 * 32 + lc * 16;

            uint32_t ahi[2][4], alo[2][4];
#pragma unroll
            for (int mf = 0; mf < 2; mf++) {
                const uint32_t roff = (uint32_t)(wm * 32 + mf * 16 + lr) * ROWB + koff;
                ldm_x4(aBaseHi + roff, ahi[mf]);
                ldm_x4(aBaseLo + roff, alo[mf]);
            }
#pragma unroll
            for (int reg = 0; reg < 4; reg++) {
                const uint32_t roff = (uint32_t)(wn * 64 + reg * 16 + lr) * ROWB + koff;
                uint32_t bh[4], bl2[4];
                ldm_x4(bBaseHi + roff, bh);
                ldm_x4(bBaseLo + roff, bl2);
#pragma unroll
                for (int mf = 0; mf < 2; mf++) {
                    mma_bf16(acc[mf][reg * 2 + 0], ahi[mf], bh[0], bh[2]);
                    mma_bf16(acc[mf][reg * 2 + 0], ahi[mf], bl2[0], bl2[2]);
                    mma_bf16(acc[mf][reg * 2 + 0], alo[mf], bh[0], bh[2]);
                    mma_bf16(acc[mf][reg * 2 + 1], ahi[mf], bh[1], bh[3]);
                    mma_bf16(acc[mf][reg * 2 + 1], ahi[mf], bl2[1], bl2[3]);
                    mma_bf16(acc[mf][reg * 2 + 1], alo[mf], bh[1], bh[3]);
                }
            }
        }
        __syncthreads();
    }

    const int lr4 = lid >> 2;
    const int lc2 = (lid & 3) * 2;
#pragma unroll
    for (int mf = 0; mf < 2; mf++) {
#pragma unroll
        for (int nf = 0; nf < 8; nf++) {
            const int m = mb * 128 + wm * 32 + mf * 16 + lr4;
            const int n = nb * 128 + wn * 64 + nf * 8 + lc2;
            if (n >= N) continue;
            float b0 = 0.f, b1 = 0.f;
            if (bias) { b0 = bias[n]; b1 = bias[n + 1]; }
            if (m < M) {
                float2 v = make_float2(acc[mf][nf][0] + b0, acc[mf][nf][1] + b1);
                *reinterpret_cast<float2*>(C + (long long)m * ldc + n) = v;
            }
            if (m + 8 < M) {
                float2 v = make_float2(acc[mf][nf][2] + b0, acc[mf][nf][3] + b1);
                *reinterpret_cast<float2*>(C + (long long)(m + 8) * ldc + n) = v;
            }
        }
    }
}

// =================== persistent recurrence kernel v6 (merged single pass) ====
// 128 CTAs = 4 bg(32 batch rows) x 32 cg(16 out cols). 256 threads = 8 warps
// (2 m-frags x 4 k-slices). k-concatenated operands:
//   A  = [h0 | h1]   (32 x 1024, bf16 hi/lo)
//   B0 = W0h         (16 x 512)   -> acc0  (layer0)
//   BC = [Wlx | Wlh] (16 x 1024)  -> acc1  (layer1)
// ONE cp.async group, ONE wait, ONE sync, ONE MMA loop per phase.

#define RNN_CTAS 128
#define RNN_THR 256
#define OFF_W0 0                          // W0h hi 16KB, lo 16KB
#define W0T 16384
#define OFF_WC 32768                      // Wcat hi 32KB, lo 32KB
#define WCT 32768
#define OFF_A 98304                       // A hi 64KB, lo 64KB
#define AT 65536
#define OFF_P 229376                      // P prefetch, 32x16 fp32 = 2KB
#define RNN_SMEM (OFF_P + 2048)           // 231424
#define OFF_R OFF_A                       // reduction aliases A (dead post-loop)
#define REDSTR 17

__global__ __launch_bounds__(RNN_THR, 1)
void rnn_persist(const int* __restrict__ inputs,
                 const float* __restrict__ W0,
                 const float* __restrict__ b0,
                 const float* __restrict__ Wl,
                 const float* __restrict__ bl,
                 float* __restrict__ hfin) {
    extern __shared__ char smc[];
    const uint32_t sbase = smem_u32(smc);
    float* const smf = reinterpret_cast<float*>(smc);
    const int tid = threadIdx.x;
    const int wid = tid >> 5, lid = tid & 31;
    const int bg = blockIdx.x >> 5;
    const int cg = blockIdx.x & 31;
    const int cbase = cg * 16;

    // ---- split weight slices into smem bf16 hi/lo tiles (once, swizzled) ----
    for (int i = tid; i < 16 * 512; i += RNN_THR) {
        const int r = i >> 9, k = i & 511;
        const int gc = cbase + r;
        const int ch = k >> 3;                       // 16B chunk within 512-col
        const int sub = (k & 7) * 2;
        const float v0 = W0[gc * 1024 + k];          // W0h  (x h0, layer0)
        const float vx = Wl[gc * 1024 + 512 + k];    // Wlx  (x h0, layer1)
        const float vh = Wl[gc * 1024 + k];          // Wlh  (x h1, layer1)
        // W0h: 1024B rows
        {
            const uint32_t off = r * 1024 + (((uint32_t)(ch ^ (r & 7))) << 4) + sub;
            const __nv_bfloat16 hi = __float2bfloat16(v0);
            *reinterpret_cast<__nv_bfloat16*>(smc + OFF_W0 + off) = hi;
            *reinterpret_cast<__nv_bfloat16*>(smc + OFF_W0 + W0T + off) =
                __float2bfloat16(v0 - __bfloat162float(hi));
        }
        // Wcat: 2048B rows; Wlx at chunks [0,64), Wlh at [64,128)
        {
            const uint32_t offx = r * 2048 + (((uint32_t)(ch ^ (r & 7))) << 4) + sub;
            const uint32_t offh = r * 2048 + (((uint32_t)((64 + ch) ^ (r & 7))) << 4) + sub;
            const __nv_bfloat16 hx = __float2bfloat16(vx);
            const __nv_bfloat16 hh = __float2bfloat16(vh);
            *reinterpret_cast<__nv_bfloat16*>(smc + OFF_WC + offx) = hx;
            *reinterpret_cast<__nv_bfloat16*>(smc + OFF_WC + WCT + offx) =
                __float2bfloat16(vx - __bfloat162float(hx));
            *reinterpret_cast<__nv_bfloat16*>(smc + OFF_WC + offh) = hh;
            *reinterpret_cast<__nv_bfloat16*>(smc + OFF_WC + WCT + offh) =
                __float2bfloat16(vh - __bfloat162float(hh));
        }
    }
    __syncthreads();

    const int mw = wid & 1;               // m-frag: rows mw*16..+15
    const int kw = wid >> 1;              // k-slice index 0..3
    const int lr = lid & 15, lc = lid >> 4;

    const int ecoll = tid & 15, erow = tid >> 4;
    const int ecol = cbase + ecoll;
    const float b0c = b0[ecol], blc = bl[ecol];

    const int arow = mw * 16 + lr;
    const uint32_t aRow = sbase + OFF_A + arow * 2048;
    const uint32_t bRowW0 = sbase + OFF_W0 + lr * 1024;
    const uint32_t bRowWC = sbase + OFF_WC + lr * 2048;
    const int axor = arow & 7;
    const int bxor = lr & 7;
    const int kb1 = kw * 32 + lc;         // acc1 chunk base (of 128 chunks)
    const int kb0 = kw * 16 + lc;         // acc0 chunk base (of 64 chunks)

    unsigned int* const gbar = &g_sync4[bg * 32];   // 128B-spaced counters

    for (int p = 0; p <= SS; p++) {
        float acc0[2][4] = {{0, 0, 0, 0}, {0, 0, 0, 0}};
        float acc1[2][4] = {{0, 0, 0, 0}, {0, 0, 0, 0}};

        // ---- ONE staging group: P rows + A = [h0 | h1] hi/lo ----
        if (p < SS && tid < 128) {
            const int row = tid >> 2, ch = tid & 3;
            const int tok = __ldg(inputs + p * BB + bg * 32 + row);
            const float* src = g_P + (long long)tok * HH + cbase + ch * 4;
            const uint32_t dst = sbase + OFF_P + row * 64 + ch * 16;
            asm volatile("cp.async.cg.shared.global [%0], [%1], 16;"
                         :: "r"(dst), "l"(src) : "memory");
        }
        {
            const __nv_bfloat16* h0h = g_h0bh[(p + 1) & 1];
            const __nv_bfloat16* h0l = g_h0bl[(p + 1) & 1];
            const __nv_bfloat16* h1h = g_h1bh[p & 1];
            const __nv_bfloat16* h1l = g_h1bl[p & 1];
#pragma unroll
            for (int j = 0; j < 32; j++) {
                const int idx = tid + j * 256;       // 0..8191
                const int tile = idx >> 12;          // 0=hi, 1=lo
                const int c = idx & 4095;
                const int row = c >> 7;              // 0..31
                const int ch = c & 127;              // 0..127
                const bool isH0 = ch < 64;
                const int col8 = (isH0 ? ch : ch - 64) * 8;
                const __nv_bfloat16* src =
                    (tile ? (isH0 ? h0l : h1l) : (isH0 ? h0h : h1h)) +
                    (long long)(bg * 32 + row) * HH + col8;
                const uint32_t dst = sbase + OFF_A + tile * AT + row * 2048 +
                                     (((uint32_t)(ch ^ (row & 7))) << 4);
                asm volatile("cp.async.cg.shared.global [%0], [%1], 16;"
                             :: "r"(dst), "l"(src) : "memory");
            }
            asm volatile("cp.async.commit_group;" ::: "memory");
            asm volatile("cp.async.wait_group 0;" ::: "memory");
        }
        __syncthreads();

        // ---- ONE MMA loop: acc1 over k=1024 (slice 256), acc0 over k=512 ----
#pragma unroll
        for (int i = 0; i < 16; i++) {
            // acc1: A vs Wcat
            {
                const uint32_t ac = (uint32_t)((kb1 + i * 2) ^ axor) << 4;
                const uint32_t wc = (uint32_t)((kb1 + i * 2) ^ bxor) << 4;
                uint32_t ah[4], al[4], bh[4], bl2[4];
                ldm_x4(aRow + ac, ah);
                ldm_x4(aRow + AT + ac, al);
                ldm_x4(bRowWC + wc, bh);
                ldm_x4(bRowWC + WCT + wc, bl2);
                mma_bf16(acc1[0], ah, bh[0], bh[2]);
                mma_bf16(acc1[1], ah, bh[1], bh[3]);
                mma_bf16(acc1[0], ah, bl2[0], bl2[2]);
                mma_bf16(acc1[1], ah, bl2[1], bl2[3]);
                mma_bf16(acc1[0], al, bh[0], bh[2]);
                mma_bf16(acc1[1], al, bh[1], bh[3]);
            }
            // acc0: h0 region vs W0h (first 8 iters cover this warp's 128 cols)
            if (i < 8) {
                const uint32_t ac = (uint32_t)((kb0 + i * 2) ^ axor) << 4;
                const uint32_t wc = (uint32_t)((kb0 + i * 2) ^ bxor) << 4;
                uint32_t ah[4], al[4], bh[4], bl2[4];
                ldm_x4(aRow + ac, ah);
                ldm_x4(aRow + AT + ac, al);
                ldm_x4(bRowW0 + wc, bh);
                ldm_x4(bRowW0 + W0T + wc, bl2);
                mma_bf16(acc0[0], ah, bh[0], bh[2]);
                mma_bf16(acc0[1], ah, bh[1], bh[3]);
                mma_bf16(acc0[0], ah, bl2[0], bl2[2]);
                mma_bf16(acc0[1], ah, bl2[1], bl2[3]);
                mma_bf16(acc0[0], al, bh[0], bh[2]);
                mma_bf16(acc0[1], al, bh[1], bh[3]);
            }
        }
        __syncthreads();   // A reads done -> red alias safe

        // ---- write k-slice frags to red (aliases A buffer) ----
        {
            const int rg = lid >> 2, cc = (lid & 3) * 2;
            float* red = smf + OFF_R / 4;
            const int m = mw * 16 + rg;
#pragma unroll
            for (int nf = 0; nf < 2; nf++) {
                const int n = nf * 8 + cc;
                float* r0 = red + ((0 * 4 + kw) * 32 + m) * REDSTR + n;
                float* r1 = red + ((1 * 4 + kw) * 32 + m) * REDSTR + n;
                r0[0] = acc0[nf][0]; r0[1] = acc0[nf][1];
                r0[8 * REDSTR] = acc0[nf][2]; r0[8 * REDSTR + 1] = acc0[nf][3];
                r1[0] = acc1[nf][0]; r1[1] = acc1[nf][1];
                r1[8 * REDSTR] = acc1[nf][2]; r1[8 * REDSTR + 1] = acc1[nf][3];
            }
        }
        __syncthreads();

        // ---- epilogue: reduce, tanh, store h state; arrive; then tops ----
        __nv_bfloat16 hv1s[2], lv1s[2];
        {
            float* red = smf + OFF_R / 4;
            const float* smP = smf + OFF_P / 4;
#pragma unroll
            for (int e = 0; e < 2; e++) {
                const int row = erow + e * 16;
                const int gbr = bg * 32 + row;
                float s0 = 0.f, s1 = 0.f;
#pragma unroll
                for (int q = 0; q < 4; q++) {
                    s0 += red[((0 * 4 + q) * 32 + row) * REDSTR + ecoll];
                    s1 += red[((1 * 4 + q) * 32 + row) * REDSTR + ecoll];
                }
                const long long o = (long long)gbr * HH + ecol;
                if (p < SS) {
                    const float v = tanhf(s0 + smP[row * 16 + ecoll] + b0c);
                    const __nv_bfloat16 hv = __float2bfloat16(v);
                    const __nv_bfloat16 lv = __float2bfloat16(v - __bfloat162float(hv));
                    g_h0bh[p & 1][o] = hv;
                    g_h0bl[p & 1][o] = lv;
                    if (p == SS - 1) hfin[o] = v;
                }
                if (p >= 1) {
                    const float v = tanhf(s1 + blc);
                    const __nv_bfloat16 hv = __float2bfloat16(v);
                    const __nv_bfloat16 lv = __float2bfloat16(v - __bfloat162float(hv));
                    g_h1bh[(p + 1) & 1][o] = hv;
                    g_h1bl[(p + 1) & 1][o] = lv;
                    hv1s[e] = hv; lv1s[e] = lv;
                    if (p == SS) hfin[BB * HH + o] = v;
                }
            }
        }

        // arrive on the bg-local barrier BEFORE the tops stores
        if (p < SS) {
            __syncthreads();
            if (tid == 0) {
                asm volatile("red.release.gpu.global.add.u32 [%0], 1;"
                             :: "l"(gbar) : "memory");
            }
        }

        if (p >= 1) {
            const int s = p - 1;
#pragma unroll
            for (int e = 0; e < 2; e++) {
                const int gbr = bg * 32 + erow + e * 16;
                const long long ot = ((long long)s * BB + gbr) * HH + ecol;
                g_Thi[ot] = hv1s[e];
                g_Tlo[ot] = lv1s[e];
            }
        }

        if (p < SS) {
            if (tid == 0) {
                const unsigned int target = (unsigned)(p + 1) * 32;
                unsigned int v;
                do {
                    asm volatile("ld.acquire.gpu.global.u32 %0, [%1];"
                                 : "=r"(v) : "l"(gbar) : "memory");
                } while (v < target);
            }
            __syncthreads();
        }
    }
}

// ---------------- prep kernels -----------------------------------------------
__global__ void prep_w0x(const float* __restrict__ W0) {
    int idx = blockIdx.x * blockDim.x + threadIdx.x;
    if (idx >= HH * EE) return;
    int c = idx / EE;
    int e = idx % EE;
    float v = W0[c * (HH + EE) + HH + e];
    __nv_bfloat16 hi = __float2bfloat16(v);
    g_Xhi[c * EE + e] = hi;
    g_Xlo[c * EE + e] = __float2bfloat16(v - __bfloat162float(hi));
}

__global__ void split_arr(const float* __restrict__ src, __nv_bfloat16* __restrict__ hi,
                          __nv_bfloat16* __restrict__ lo, int n, float scale) {
    int i = blockIdx.x * blockDim.x + threadIdx.x;
    if (i >= n) return;
    float v = src[i] * scale;
    __nv_bfloat16 h = __float2bfloat16(v);
    hi[i] = h;
    lo[i] = __float2bfloat16(v - __bfloat162float(h));
}

__global__ void init_state(const float* __restrict__ hidden) {
    int i = blockIdx.x * blockDim.x + threadIdx.x;
    if (i < 128) g_sync4[i] = 0;
    if (i < BB * HH) {
        float v0 = hidden[i];
        __nv_bfloat16 h0 = __float2bfloat16(v0);
        g_h0bh[1][i] = h0;
        g_h0bl[1][i] = __float2bfloat16(v0 - __bfloat162float(h0));
        float v1 = hidden[BB * HH + i];
        __nv_bfloat16 h1 = __float2bfloat16(v1);
        g_h1bh[1][i] = h1;
        g_h1bl[1][i] = __float2bfloat16(v1 - __bfloat162float(h1));
    }
}

// ---------------- launch ------------------------------------------------------
extern "C" void kernel_launch(void* const* d_in, const int* in_sizes, int n_in,
                              void* d_out, int out_size) {
    const int*   inputs = (const int*)  d_in[0];
    const float* hidden = (const float*)d_in[1];
    const float* emb    = (const float*)d_in[2];
    const float* W0     = (const float*)d_in[3];
    const float* b0     = (const float*)d_in[4];
    const float* Wl     = (const float*)d_in[5];
    const float* bl     = (const float*)d_in[6];
    const float* Wout   = (const float*)d_in[7];
    const float* bout   = (const float*)d_in[8];

    float* logits = (float*)d_out;
    float* hfin   = (float*)d_out + (long long)SS * BB * VV;

    cudaFuncSetAttribute(gemm_hmma, cudaFuncAttributeMaxDynamicSharedMemorySize,
                         GEMM_SMEM);
    cudaFuncSetAttribute(rnn_persist, cudaFuncAttributeMaxDynamicSharedMemorySize,
                         RNN_SMEM);

    float* pP = nullptr;
    cudaGetSymbolAddress((void**)&pP, g_P);
    __nv_bfloat16 *pThi, *pTlo, *pWhi, *pWlo, *pEhi, *pElo, *pXhi, *pXlo;
    cudaGetSymbolAddress((void**)&pThi, g_Thi);
    cudaGetSymbolAddress((void**)&pTlo, g_Tlo);
    cudaGetSymbolAddress((void**)&pWhi, g_Whi);
    cudaGetSymbolAddress((void**)&pWlo, g_Wlo);
    cudaGetSymbolAddress((void**)&pEhi, g_Ehi);
    cudaGetSymbolAddress((void**)&pElo, g_Elo);
    cudaGetSymbolAddress((void**)&pXhi, g_Xhi);
    cudaGetSymbolAddress((void**)&pXlo, g_Xlo);

    const float scale = 22.62741699796952f;  // sqrt(512)

    // 1. prep
    init_state<<<(BB * HH + 255) / 256, 256>>>(hidden);
    prep_w0x<<<(HH * EE + 255) / 256, 256>>>(W0);
    split_arr<<<(VV * EE + 255) / 256, 256>>>(emb, pEhi, pElo, VV * EE, scale);
    split_arr<<<(VV * HH + 255) / 256, 256>>>(Wout, pWhi, pWlo, VV * HH, 1.0f);

    // 2. P = scale*emb @ W0x^T  (M=10000, N=512, K=512)
    {
        dim3 grid((HH + 127) / 128, (VV + 127) / 128);
        gemm_hmma<<<grid, 256, GEMM_SMEM>>>(pEhi, pElo, pXhi, pXlo,
                                            VV, HH, pP, HH, nullptr);
    }

    // 3. full recurrence in ONE persistent kernel (tensor cores, merged pass)
    rnn_persist<<<RNN_CTAS, RNN_THR, RNN_SMEM>>>(inputs, W0, b0, Wl, bl, hfin);

    // 4. logits = tops @ Wout^T + bout  (M=16384, N=10000, K=512)
    {
        dim3 grid((VV + 127) / 128, (SS * BB + 127) / 128);
        gemm_hmma<<<grid, 256, GEMM_SMEM>>>(pThi, pTlo, pWhi, pWlo,
                                            SS * BB, VV, logits, VV, bout);
    }
}

// round 13
// speedup vs baseline: 1.2756x; 1.2756x over previous
#include <cuda_runtime.h>
#include <cuda_bf16.h>
#include <cuda_fp16.h>
#include <math.h>
#include <stdint.h>

#define SS 128
#define BB 128
#define VV 10000
#define HH 512
#define EE 512
#define KDIM 512

// ---------------- scratch (device globals: no allocations allowed) ----------
__device__ float g_P[VV * HH];          // scale * emb @ W0_x^T
__device__ unsigned int g_sync4[128];   // 4 batch-group barriers, 128B apart
// hidden state as bf16 hi/lo ping-pong (MMA operands)
__device__ __nv_bfloat16 g_h0bh[2][BB * HH], g_h0bl[2][BB * HH];
__device__ __nv_bfloat16 g_h1bh[2][BB * HH], g_h1bl[2][BB * HH];
// fp16 operands for the logits GEMM (A split hi/lo, B single)
__device__ __half g_Thi[SS * BB * HH];
__device__ __half g_Tlo[SS * BB * HH];
__device__ __half g_W16[VV * HH];
// bf16 hi/lo split operands for the P GEMM
__device__ __nv_bfloat16 g_Ehi[VV * EE];
__device__ __nv_bfloat16 g_Elo[VV * EE];
__device__ __nv_bfloat16 g_Xhi[HH * EE];
__device__ __nv_bfloat16 g_Xlo[HH * EE];

// ============================ helpers ========================================
__device__ __forceinline__ uint32_t smem_u32(const void* p) {
    uint32_t a;
    asm("{ .reg .u64 t; cvta.to.shared.u64 t, %1; cvt.u32.u64 %0, t; }"
        : "=r"(a) : "l"(p));
    return a;
}

__device__ __forceinline__ void ldm_x4(uint32_t addr, uint32_t r[4]) {
    asm volatile("ldmatrix.sync.aligned.m8n8.x4.shared.b16 {%0,%1,%2,%3}, [%4];"
                 : "=r"(r[0]), "=r"(r[1]), "=r"(r[2]), "=r"(r[3]) : "r"(addr));
}

__device__ __forceinline__ void mma_bf16(float c[4], const uint32_t a[4],
                                         uint32_t b0, uint32_t b1) {
    asm volatile(
        "mma.sync.aligned.m16n8k16.row.col.f32.bf16.bf16.f32 "
        "{%0,%1,%2,%3}, {%4,%5,%6,%7}, {%8,%9}, {%0,%1,%2,%3};"
        : "+f"(c[0]), "+f"(c[1]), "+f"(c[2]), "+f"(c[3])
        : "r"(a[0]), "r"(a[1]), "r"(a[2]), "r"(a[3]), "r"(b0), "r"(b1));
}

__device__ __forceinline__ void mma_fp16(float c[4], const uint32_t a[4],
                                         uint32_t b0, uint32_t b1) {
    asm volatile(
        "mma.sync.aligned.m16n8k16.row.col.f32.f16.f16.f32 "
        "{%0,%1,%2,%3}, {%4,%5,%6,%7}, {%8,%9}, {%0,%1,%2,%3};"
        : "+f"(c[0]), "+f"(c[1]), "+f"(c[2]), "+f"(c[3])
        : "r"(a[0]), "r"(a[1]), "r"(a[2]), "r"(a[3]), "r"(b0), "r"(b1));
}

// =================== bf16-split HMMA GEMM (3-pass, for P) ====================
#define BK 32
#define ROWB 80
#define TILE_SB (128 * ROWB)
#define STAGE_SB (4 * TILE_SB)
#define GEMM_SMEM (2 * STAGE_SB)       // 81920
#define KT_N (KDIM / BK)               // 16

__global__ __launch_bounds__(256, 2)
void gemm_hmma(const __nv_bfloat16* __restrict__ Ahi,
               const __nv_bfloat16* __restrict__ Alo,
               const __nv_bfloat16* __restrict__ Bhi,
               const __nv_bfloat16* __restrict__ Blo,
               int M, int N, float* __restrict__ C, int ldc,
               const float* __restrict__ bias) {
    extern __shared__ char smem[];
    const uint32_t sb = smem_u32(smem);
    const int tid = threadIdx.x;
    const int wid = tid >> 5, lid = tid & 31;
    const int wm = wid & 3, wn = wid >> 2;
    const int nb = blockIdx.x, mb = blockIdx.y;

    const __nv_bfloat16* __restrict__ srcs[4] = {Ahi, Alo, Bhi, Blo};

    float acc[2][8][4];
#pragma unroll
    for (int i = 0; i < 2; i++)
#pragma unroll
        for (int j = 0; j < 8; j++)
#pragma unroll
            for (int q = 0; q < 4; q++) acc[i][j][q] = 0.0f;

    auto load_stage = [&](int st, int kt) {
#pragma unroll
        for (int t = 0; t < 4; t++) {
#pragma unroll
            for (int i = 0; i < 2; i++) {
                const int idx = tid + i * 256;
                const int row = idx >> 2, ch = idx & 3;
                const long long grow =
                    (t < 2) ? (long long)mb * 128 + row : (long long)nb * 128 + row;
                const bool ok = (t < 2) ? (grow < M) : (grow < N);
                const __nv_bfloat16* src = srcs[t] + grow * KDIM + kt * BK + ch * 8;
                const uint32_t dst = sb + st * STAGE_SB + t * TILE_SB + row * ROWB + ch * 16;
                const int sz = ok ? 16 : 0;
                asm volatile("cp.async.cg.shared.global [%0], [%1], 16, %2;"
                             :: "r"(dst), "l"(src), "r"(sz) : "memory");
            }
        }
        asm volatile("cp.async.commit_group;" ::: "memory");
    };

    const int lr = lid & 15;
    const int lc = lid >> 4;

    load_stage(0, 0);

    for (int kt = 0; kt < KT_N; kt++) {
        const int st = kt & 1;
        if (kt + 1 < KT_N) {
            load_stage(st ^ 1, kt + 1);
            asm volatile("cp.async.wait_group 1;" ::: "memory");
        } else {
            asm volatile("cp.async.wait_group 0;" ::: "memory");
        }
        __syncthreads();

        const uint32_t stg = sb + st * STAGE_SB;
        const uint32_t aBaseHi = stg + 0 * TILE_SB;
        const uint32_t aBaseLo = stg + 1 * TILE_SB;
        const uint32_t bBaseHi = stg + 2 * TILE_SB;
        const uint32_t bBaseLo = stg + 3 * TILE_SB;

#pragma unroll
        for (int k16 = 0; k16 < 2; k16++) {
            const uint32_t koff = k16 * 32 + lc * 16;

            uint32_t ahi[2][4], alo[2][4];
#pragma unroll
            for (int mf = 0; mf < 2; mf++) {
                const uint32_t roff = (uint32_t)(wm * 32 + mf * 16 + lr) * ROWB + koff;
                ldm_x4(aBaseHi + roff, ahi[mf]);
                ldm_x4(aBaseLo + roff, alo[mf]);
            }
#pragma unroll
            for (int reg = 0; reg < 4; reg++) {
                const uint32_t roff = (uint32_t)(wn * 64 + reg * 16 + lr) * ROWB + koff;
                uint32_t bh[4], bl2[4];
                ldm_x4(bBaseHi + roff, bh);
                ldm_x4(bBaseLo + roff, bl2);
#pragma unroll
                for (int mf = 0; mf < 2; mf++) {
                    mma_bf16(acc[mf][reg * 2 + 0], ahi[mf], bh[0], bh[2]);
                    mma_bf16(acc[mf][reg * 2 + 0], ahi[mf], bl2[0], bl2[2]);
                    mma_bf16(acc[mf][reg * 2 + 0], alo[mf], bh[0], bh[2]);
                    mma_bf16(acc[mf][reg * 2 + 1], ahi[mf], bh[1], bh[3]);
                    mma_bf16(acc[mf][reg * 2 + 1], ahi[mf], bl2[1], bl2[3]);
                    mma_bf16(acc[mf][reg * 2 + 1], alo[mf], bh[1], bh[3]);
                }
            }
        }
        __syncthreads();
    }

    const int lr4 = lid >> 2;
    const int lc2 = (lid & 3) * 2;
#pragma unroll
    for (int mf = 0; mf < 2; mf++) {
#pragma unroll
        for (int nf = 0; nf < 8; nf++) {
            const int m = mb * 128 + wm * 32 + mf * 16 + lr4;
            const int n = nb * 128 + wn * 64 + nf * 8 + lc2;
            if (n >= N) continue;
            float b0 = 0.f, b1 = 0.f;
            if (bias) { b0 = bias[n]; b1 = bias[n + 1]; }
            if (m < M) {
                float2 v = make_float2(acc[mf][nf][0] + b0, acc[mf][nf][1] + b1);
                *reinterpret_cast<float2*>(C + (long long)m * ldc + n) = v;
            }
            if (m + 8 < M) {
                float2 v = make_float2(acc[mf][nf][2] + b0, acc[mf][nf][3] + b1);
                *reinterpret_cast<float2*>(C + (long long)(m + 8) * ldc + n) = v;
            }
        }
    }
}

// =================== fp16 2-pass HMMA GEMM (logits) ==========================
// C = (Ahi+Alo) @ Bh^T + bias; A split fp16 (exact to ~2^-22), B single fp16.
// 3 tiles/stage (Ahi, Alo, Bh) = 30KB/stage, 2 stages, 2 CTAs/SM.
#define F16_STAGE (3 * TILE_SB)          // 30720
#define F16_SMEM (2 * F16_STAGE)         // 61440

__global__ __launch_bounds__(256, 2)
void gemm_fp16(const __half* __restrict__ Ahi,
               const __half* __restrict__ Alo,
               const __half* __restrict__ Bh,
               int M, int N, float* __restrict__ C, int ldc,
               const float* __restrict__ bias) {
    extern __shared__ char smem[];
    const uint32_t sb = smem_u32(smem);
    const int tid = threadIdx.x;
    const int wid = tid >> 5, lid = tid & 31;
    const int wm = wid & 3, wn = wid >> 2;
    const int nb = blockIdx.x, mb = blockIdx.y;

    const __half* __restrict__ srcs[3] = {Ahi, Alo, Bh};

    float acc[2][8][4];
#pragma unroll
    for (int i = 0; i < 2; i++)
#pragma unroll
        for (int j = 0; j < 8; j++)
#pragma unroll
            for (int q = 0; q < 4; q++) acc[i][j][q] = 0.0f;

    auto load_stage = [&](int st, int kt) {
        // 3 tiles x 128 rows x 4 chunks = 1536 cp.asyncs; 6 per thread
#pragma unroll
        for (int t = 0; t < 3; t++) {
#pragma unroll
            for (int i = 0; i < 2; i++) {
                const int idx = tid + i * 256;
                const int row = idx >> 2, ch = idx & 3;
                const long long grow =
                    (t < 2) ? (long long)mb * 128 + row : (long long)nb * 128 + row;
                const bool ok = (t < 2) ? (grow < M) : (grow < N);
                const __half* src = srcs[t] + grow * KDIM + kt * BK + ch * 8;
                const uint32_t dst = sb + st * F16_STAGE + t * TILE_SB + row * ROWB + ch * 16;
                const int sz = ok ? 16 : 0;
                asm volatile("cp.async.cg.shared.global [%0], [%1], 16, %2;"
                             :: "r"(dst), "l"(src), "r"(sz) : "memory");
            }
        }
        asm volatile("cp.async.commit_group;" ::: "memory");
    };

    const int lr = lid & 15;
    const int lc = lid >> 4;

    load_stage(0, 0);

    for (int kt = 0; kt < KT_N; kt++) {
        const int st = kt & 1;
        if (kt + 1 < KT_N) {
            load_stage(st ^ 1, kt + 1);
            asm volatile("cp.async.wait_group 1;" ::: "memory");
        } else {
            asm volatile("cp.async.wait_group 0;" ::: "memory");
        }
        __syncthreads();

        const uint32_t stg = sb + st * F16_STAGE;
        const uint32_t aBaseHi = stg + 0 * TILE_SB;
        const uint32_t aBaseLo = stg + 1 * TILE_SB;
        const uint32_t bBase = stg + 2 * TILE_SB;

#pragma unroll
        for (int k16 = 0; k16 < 2; k16++) {
            const uint32_t koff = k16 * 32 + lc * 16;

            uint32_t ahi[2][4], alo[2][4];
#pragma unroll
            for (int mf = 0; mf < 2; mf++) {
                const uint32_t roff = (uint32_t)(wm * 32 + mf * 16 + lr) * ROWB + koff;
                ldm_x4(aBaseHi + roff, ahi[mf]);
                ldm_x4(aBaseLo + roff, alo[mf]);
            }
#pragma unroll
            for (int reg = 0; reg < 4; reg++) {
                const uint32_t roff = (uint32_t)(wn * 64 + reg * 16 + lr) * ROWB + koff;
                uint32_t bh[4];
                ldm_x4(bBase + roff, bh);
#pragma unroll
                for (int mf = 0; mf < 2; mf++) {
                    mma_fp16(acc[mf][reg * 2 + 0], ahi[mf], bh[0], bh[2]);
                    mma_fp16(acc[mf][reg * 2 + 0], alo[mf], bh[0], bh[2]);
                    mma_fp16(acc[mf][reg * 2 + 1], ahi[mf], bh[1], bh[3]);
                    mma_fp16(acc[mf][reg * 2 + 1], alo[mf], bh[1], bh[3]);
                }
            }
        }
        __syncthreads();
    }

    const int lr4 = lid >> 2;
    const int lc2 = (lid & 3) * 2;
#pragma unroll
    for (int mf = 0; mf < 2; mf++) {
#pragma unroll
        for (int nf = 0; nf < 8; nf++) {
            const int m = mb * 128 + wm * 32 + mf * 16 + lr4;
            const int n = nb * 128 + wn * 64 + nf * 8 + lc2;
            if (n >= N) continue;
            float b0 = 0.f, b1 = 0.f;
            if (bias) { b0 = bias[n]; b1 = bias[n + 1]; }
            if (m < M) {
                float2 v = make_float2(acc[mf][nf][0] + b0, acc[mf][nf][1] + b1);
                *reinterpret_cast<float2*>(C + (long long)m * ldc + n) = v;
            }
            if (m + 8 < M) {
                float2 v = make_float2(acc[mf][nf][2] + b0, acc[mf][nf][3] + b1);
                *reinterpret_cast<float2*>(C + (long long)(m + 8) * ldc + n) = v;
            }
        }
    }
}

// =================== persistent recurrence kernel v5 (tensor cores) =========
// (reverted R11 structure: separate h0/h1 buffers, overlapped staging,
//  bg-local barriers, P prefetch; tops emitted as fp16 hi/lo)

#define RNN_CTAS 128
#define RNN_THR 256
#define WT16 16384
#define HT32 32768
#define OFF_W 0
#define OFF_H0 (6 * WT16)
#define OFF_H1 (OFF_H0 + 2 * HT32)
#define OFF_P (OFF_H1 + 2 * HT32)         // 229376: P prefetch, 32x16 fp32
#define RNN_SMEM (OFF_P + 2048)           // 231424
#define OFF_R OFF_H0
#define REDSTR 17

__global__ __launch_bounds__(RNN_THR, 1)
void rnn_persist(const int* __restrict__ inputs,
                 const float* __restrict__ W0,
                 const float* __restrict__ b0,
                 const float* __restrict__ Wl,
                 const float* __restrict__ bl,
                 float* __restrict__ hfin) {
    extern __shared__ char smc[];
    const uint32_t sbase = smem_u32(smc);
    float* const smf = reinterpret_cast<float*>(smc);
    const int tid = threadIdx.x;
    const int wid = tid >> 5, lid = tid & 31;
    const int bg = blockIdx.x >> 5;
    const int cg = blockIdx.x & 31;
    const int cbase = cg * 16;

    for (int i = tid; i < 16 * 512; i += RNN_THR) {
        const int r = i >> 9, k = i & 511;
        const int gc = cbase + r;
        const uint32_t off = r * 1024 + (((k >> 3) ^ (r & 7)) << 4) + (k & 7) * 2;
        float v[3];
        v[0] = W0[gc * 1024 + k];
        v[1] = Wl[gc * 1024 + 512 + k];
        v[2] = Wl[gc * 1024 + k];
#pragma unroll
        for (int t = 0; t < 3; t++) {
            const __nv_bfloat16 hi = __float2bfloat16(v[t]);
            const __nv_bfloat16 lo = __float2bfloat16(v[t] - __bfloat162float(hi));
            char* base = smc + OFF_W + (2 * t) * WT16 + off;
            *reinterpret_cast<__nv_bfloat16*>(base) = hi;
            *reinterpret_cast<__nv_bfloat16*>(base + WT16) = lo;
        }
    }
    __syncthreads();

    const int mw = wid & 1;
    const int kw = wid >> 1;
    const int lr = lid & 15, lc = lid >> 4;

    const int ecoll = tid & 15, erow = tid >> 4;
    const int ecol = cbase + ecoll;
    const float b0c = b0[ecol], blc = bl[ecol];

    const int arow = mw * 16 + lr;
    const uint32_t aRowH0 = sbase + OFF_H0 + arow * 1024;
    const uint32_t aRowH1 = sbase + OFF_H1 + arow * 1024;
    const uint32_t bRow = sbase + OFF_W + lr * 1024;
    const int axor = arow & 7;
    const int bxor = lr & 7;
    const int c0 = kw * 16 + lc;

    unsigned int* const gbar = &g_sync4[bg * 32];

    auto stage_h = [&](uint32_t offBase, const __nv_bfloat16* hi,
                       const __nv_bfloat16* lo) {
#pragma unroll
        for (int j = 0; j < 16; j++) {
            const int idx = tid + j * 256;
            const int tile = idx >> 11;
            const int c = idx & 2047;
            const int row = c >> 6, ch = c & 63;
            const __nv_bfloat16* src =
                (tile ? lo : hi) + (long long)(bg * 32 + row) * HH + ch * 8;
            const uint32_t dst = sbase + offBase + tile * HT32 + row * 1024 +
                                 ((ch ^ (row & 7)) << 4);
            asm volatile("cp.async.cg.shared.global [%0], [%1], 16;"
                         :: "r"(dst), "l"(src) : "memory");
        }
        asm volatile("cp.async.commit_group;" ::: "memory");
    };

    for (int p = 0; p <= SS; p++) {
        float acc0[2][4] = {{0, 0, 0, 0}, {0, 0, 0, 0}};
        float acc1[2][4] = {{0, 0, 0, 0}, {0, 0, 0, 0}};

        if (p < SS && tid < 128) {
            const int row = tid >> 2, ch = tid & 3;
            const int tok = __ldg(inputs + p * BB + bg * 32 + row);
            const float* src = g_P + (long long)tok * HH + cbase + ch * 4;
            const uint32_t dst = sbase + OFF_P + row * 64 + ch * 16;
            asm volatile("cp.async.cg.shared.global [%0], [%1], 16;"
                         :: "r"(dst), "l"(src) : "memory");
        }
        stage_h(OFF_H0, g_h0bh[(p + 1) & 1], g_h0bl[(p + 1) & 1]);   // grp 0
        stage_h(OFF_H1, g_h1bh[p & 1], g_h1bl[p & 1]);               // grp 1
        asm volatile("cp.async.wait_group 1;" ::: "memory");         // P+h0 ready
        __syncthreads();

        // ---- pass A: h0 x W0h -> acc0 ; h0 x Wlx -> acc1 ----
#pragma unroll
        for (int i = 0; i < 8; i++) {
            const uint32_t sc = (uint32_t)((c0 + i * 2) ^ axor) << 4;
            const uint32_t wc = (uint32_t)((c0 + i * 2) ^ bxor) << 4;
            uint32_t ah[4], al[4], b0h[4], b0l[4], bxh[4], bxl[4];
            ldm_x4(aRowH0 + sc, ah);
            ldm_x4(aRowH0 + HT32 + sc, al);
            ldm_x4(bRow + 0 * WT16 + wc, b0h);
            ldm_x4(bRow + 1 * WT16 + wc, b0l);
            ldm_x4(bRow + 2 * WT16 + wc, bxh);
            ldm_x4(bRow + 3 * WT16 + wc, bxl);
            mma_bf16(acc0[0], ah, b0h[0], b0h[2]);
            mma_bf16(acc0[1], ah, b0h[1], b0h[3]);
            mma_bf16(acc0[0], ah, b0l[0], b0l[2]);
            mma_bf16(acc0[1], ah, b0l[1], b0l[3]);
            mma_bf16(acc0[0], al, b0h[0], b0h[2]);
            mma_bf16(acc0[1], al, b0h[1], b0h[3]);
            mma_bf16(acc1[0], ah, bxh[0], bxh[2]);
            mma_bf16(acc1[1], ah, bxh[1], bxh[3]);
            mma_bf16(acc1[0], ah, bxl[0], bxl[2]);
            mma_bf16(acc1[1], ah, bxl[1], bxl[3]);
            mma_bf16(acc1[0], al, bxh[0], bxh[2]);
            mma_bf16(acc1[1], al, bxh[1], bxh[3]);
        }

        asm volatile("cp.async.wait_group 0;" ::: "memory");   // h1 ready
        __syncthreads();

        // ---- pass B: h1 x Wlh -> acc1 ----
#pragma unroll
        for (int i = 0; i < 8; i++) {
            const uint32_t sc = (uint32_t)((c0 + i * 2) ^ axor) << 4;
            const uint32_t wc = (uint32_t)((c0 + i * 2) ^ bxor) << 4;
            uint32_t ah[4], al[4], bhh[4], bhl[4];
            ldm_x4(aRowH1 + sc, ah);
            ldm_x4(aRowH1 + HT32 + sc, al);
            ldm_x4(bRow + 4 * WT16 + wc, bhh);
            ldm_x4(bRow + 5 * WT16 + wc, bhl);
            mma_bf16(acc1[0], ah, bhh[0], bhh[2]);
            mma_bf16(acc1[1], ah, bhh[1], bhh[3]);
            mma_bf16(acc1[0], ah, bhl[0], bhl[2]);
            mma_bf16(acc1[1], ah, bhl[1], bhl[3]);
            mma_bf16(acc1[0], al, bhh[0], bhh[2]);
            mma_bf16(acc1[1], al, bhh[1], bhh[3]);
        }

        // ---- write k-slice frags to red (aliases h0 buffer) ----
        {
            const int rg = lid >> 2, cc = (lid & 3) * 2;
            float* red = smf + OFF_R / 4;
            const int m = mw * 16 + rg;
#pragma unroll
            for (int nf = 0; nf < 2; nf++) {
                const int n = nf * 8 + cc;
                float* r0 = red + ((0 * 4 + kw) * 32 + m) * REDSTR + n;
                float* r1 = red + ((1 * 4 + kw) * 32 + m) * REDSTR + n;
                r0[0] = acc0[nf][0]; r0[1] = acc0[nf][1];
                r0[8 * REDSTR] = acc0[nf][2]; r0[8 * REDSTR + 1] = acc0[nf][3];
                r1[0] = acc1[nf][0]; r1[1] = acc1[nf][1];
                r1[8 * REDSTR] = acc1[nf][2]; r1[8 * REDSTR + 1] = acc1[nf][3];
            }
        }
        __syncthreads();

        // ---- epilogue ----
        __half hv1s[2], lv1s[2];
        {
            float* red = smf + OFF_R / 4;
            const float* smP = smf + OFF_P / 4;
#pragma unroll
            for (int e = 0; e < 2; e++) {
                const int row = erow + e * 16;
                const int gbr = bg * 32 + row;
                float s0 = 0.f, s1 = 0.f;
#pragma unroll
                for (int q = 0; q < 4; q++) {
                    s0 += red[((0 * 4 + q) * 32 + row) * REDSTR + ecoll];
                    s1 += red[((1 * 4 + q) * 32 + row) * REDSTR + ecoll];
                }
                const long long o = (long long)gbr * HH + ecol;
                if (p < SS) {
                    const float v = tanhf(s0 + smP[row * 16 + ecoll] + b0c);
                    const __nv_bfloat16 hv = __float2bfloat16(v);
                    const __nv_bfloat16 lv = __float2bfloat16(v - __bfloat162float(hv));
                    g_h0bh[p & 1][o] = hv;
                    g_h0bl[p & 1][o] = lv;
                    if (p == SS - 1) hfin[o] = v;
                }
                if (p >= 1) {
                    const float v = tanhf(s1 + blc);
                    const __nv_bfloat16 hv = __float2bfloat16(v);
                    const __nv_bfloat16 lv = __float2bfloat16(v - __bfloat162float(hv));
                    g_h1bh[(p + 1) & 1][o] = hv;
                    g_h1bl[(p + 1) & 1][o] = lv;
                    // fp16 split for the logits GEMM
                    const __half h16 = __float2half(v);
                    hv1s[e] = h16;
                    lv1s[e] = __float2half(v - __half2float(h16));
                    if (p == SS) hfin[BB * HH + o] = v;
                }
            }
        }

        if (p < SS) {
            __syncthreads();
            if (tid == 0) {
                asm volatile("red.release.gpu.global.add.u32 [%0], 1;"
                             :: "l"(gbar) : "memory");
            }
        }

        if (p >= 1) {
            const int s = p - 1;
#pragma unroll
            for (int e = 0; e < 2; e++) {
                const int gbr = bg * 32 + erow + e * 16;
                const long long ot = ((long long)s * BB + gbr) * HH + ecol;
                g_Thi[ot] = hv1s[e];
                g_Tlo[ot] = lv1s[e];
            }
        }

        if (p < SS) {
            if (tid == 0) {
                const unsigned int target = (unsigned)(p + 1) * 32;
                unsigned int v;
                do {
                    asm volatile("ld.acquire.gpu.global.u32 %0, [%1];"
                                 : "=r"(v) : "l"(gbar) : "memory");
                } while (v < target);
            }
            __syncthreads();
        }
    }
}

// ---------------- prep kernels -----------------------------------------------
__global__ void prep_w0x(const float* __restrict__ W0) {
    int idx = blockIdx.x * blockDim.x + threadIdx.x;
    if (idx >= HH * EE) return;
    int c = idx / EE;
    int e = idx % EE;
    float v = W0[c * (HH + EE) + HH + e];
    __nv_bfloat16 hi = __float2bfloat16(v);
    g_Xhi[c * EE + e] = hi;
    g_Xlo[c * EE + e] = __float2bfloat16(v - __bfloat162float(hi));
}

__global__ void split_arr(const float* __restrict__ src, __nv_bfloat16* __restrict__ hi,
                          __nv_bfloat16* __restrict__ lo, int n, float scale) {
    int i = blockIdx.x * blockDim.x + threadIdx.x;
    if (i >= n) return;
    float v = src[i] * scale;
    __nv_bfloat16 h = __float2bfloat16(v);
    hi[i] = h;
    lo[i] = __float2bfloat16(v - __bfloat162float(h));
}

__global__ void conv_fp16(const float* __restrict__ src, __half* __restrict__ dst,
                          int n) {
    int i = blockIdx.x * blockDim.x + threadIdx.x;
    if (i < n) dst[i] = __float2half(src[i]);
}

__global__ void init_state(const float* __restrict__ hidden) {
    int i = blockIdx.x * blockDim.x + threadIdx.x;
    if (i < 128) g_sync4[i] = 0;
    if (i < BB * HH) {
        float v0 = hidden[i];
        __nv_bfloat16 h0 = __float2bfloat16(v0);
        g_h0bh[1][i] = h0;
        g_h0bl[1][i] = __float2bfloat16(v0 - __bfloat162float(h0));
        float v1 = hidden[BB * HH + i];
        __nv_bfloat16 h1 = __float2bfloat16(v1);
        g_h1bh[1][i] = h1;
        g_h1bl[1][i] = __float2bfloat16(v1 - __bfloat162float(h1));
    }
}

// ---------------- launch ------------------------------------------------------
extern "C" void kernel_launch(void* const* d_in, const int* in_sizes, int n_in,
                              void* d_out, int out_size) {
    const int*   inputs = (const int*)  d_in[0];
    const float* hidden = (const float*)d_in[1];
    const float* emb    = (const float*)d_in[2];
    const float* W0     = (const float*)d_in[3];
    const float* b0     = (const float*)d_in[4];
    const float* Wl     = (const float*)d_in[5];
    const float* bl     = (const float*)d_in[6];
    const float* Wout   = (const float*)d_in[7];
    const float* bout   = (const float*)d_in[8];

    float* logits = (float*)d_out;
    float* hfin   = (float*)d_out + (long long)SS * BB * VV;

    cudaFuncSetAttribute(gemm_hmma, cudaFuncAttributeMaxDynamicSharedMemorySize,
                         GEMM_SMEM);
    cudaFuncSetAttribute(gemm_fp16, cudaFuncAttributeMaxDynamicSharedMemorySize,
                         F16_SMEM);
    cudaFuncSetAttribute(rnn_persist, cudaFuncAttributeMaxDynamicSharedMemorySize,
                         RNN_SMEM);

    float* pP = nullptr;
    cudaGetSymbolAddress((void**)&pP, g_P);
    __half *pThi, *pTlo, *pW16;
    __nv_bfloat16 *pEhi, *pElo, *pXhi, *pXlo;
    cudaGetSymbolAddress((void**)&pThi, g_Thi);
    cudaGetSymbolAddress((void**)&pTlo, g_Tlo);
    cudaGetSymbolAddress((void**)&pW16, g_W16);
    cudaGetSymbolAddress((void**)&pEhi, g_Ehi);
    cudaGetSymbolAddress((void**)&pElo, g_Elo);
    cudaGetSymbolAddress((void**)&pXhi, g_Xhi);
    cudaGetSymbolAddress((void**)&pXlo, g_Xlo);

    const float scale = 22.62741699796952f;  // sqrt(512)

    // 1. prep
    init_state<<<(BB * HH + 255) / 256, 256>>>(hidden);
    prep_w0x<<<(HH * EE + 255) / 256, 256>>>(W0);
    split_arr<<<(VV * EE + 255) / 256, 256>>>(emb, pEhi, pElo, VV * EE, scale);
    conv_fp16<<<(VV * HH + 255) / 256, 256>>>(Wout, pW16, VV * HH);

    // 2. P = scale*emb @ W0x^T  (M=10000, N=512, K=512) — bf16 3-pass
    {
        dim3 grid((HH + 127) / 128, (VV + 127) / 128);
        gemm_hmma<<<grid, 256, GEMM_SMEM>>>(pEhi, pElo, pXhi, pXlo,
                                            VV, HH, pP, HH, nullptr);
    }

    // 3. full recurrence in ONE persistent kernel (tensor cores)
    rnn_persist<<<RNN_CTAS, RNN_THR, RNN_SMEM>>>(inputs, W0, b0, Wl, bl, hfin);

    // 4. logits = tops @ Wout^T + bout  (M=16384, N=10000, K=512) — fp16 2-pass
    {
        dim3 grid((VV + 127) / 128, (SS * BB + 127) / 128);
        gemm_fp16<<<grid, 256, F16_SMEM>>>(pThi, pTlo, pW16,
                                           SS * BB, VV, logits, VV, bout);
    }
}

// round 14
// speedup vs baseline: 1.7047x; 1.3364x over previous
#include <cuda_runtime.h>
#include <cuda_bf16.h>
#include <cuda_fp16.h>
#include <math.h>
#include <stdint.h>

#define SS 128
#define BB 128
#define VV 10000
#define HH 512
#define EE 512
#define KDIM 512

// ---------------- scratch (device globals: no allocations allowed) ----------
__device__ float g_P[VV * HH];          // scale * emb @ W0_x^T
__device__ unsigned int g_sync4[128];   // 4 batch-group barriers, 128B apart
// hidden state as bf16 hi/lo ping-pong (recurrence MMA operands)
__device__ __nv_bfloat16 g_h0bh[2][BB * HH], g_h0bl[2][BB * HH];
__device__ __nv_bfloat16 g_h1bh[2][BB * HH], g_h1bl[2][BB * HH];
// fp16 operands for the logits GEMM (single-pass: A single, B single)
__device__ __half g_T16[SS * BB * HH];
__device__ __half g_W16[VV * HH];
// fp16 operands for the P GEMM (A split hi/lo exact, B single)
__device__ __half g_E16h[VV * EE];
__device__ __half g_E16l[VV * EE];
__device__ __half g_X16[HH * EE];

// ============================ helpers ========================================
__device__ __forceinline__ uint32_t smem_u32(const void* p) {
    uint32_t a;
    asm("{ .reg .u64 t; cvta.to.shared.u64 t, %1; cvt.u32.u64 %0, t; }"
        : "=r"(a) : "l"(p));
    return a;
}

__device__ __forceinline__ void ldm_x4(uint32_t addr, uint32_t r[4]) {
    asm volatile("ldmatrix.sync.aligned.m8n8.x4.shared.b16 {%0,%1,%2,%3}, [%4];"
                 : "=r"(r[0]), "=r"(r[1]), "=r"(r[2]), "=r"(r[3]) : "r"(addr));
}

__device__ __forceinline__ void mma_bf16(float c[4], const uint32_t a[4],
                                         uint32_t b0, uint32_t b1) {
    asm volatile(
        "mma.sync.aligned.m16n8k16.row.col.f32.bf16.bf16.f32 "
        "{%0,%1,%2,%3}, {%4,%5,%6,%7}, {%8,%9}, {%0,%1,%2,%3};"
        : "+f"(c[0]), "+f"(c[1]), "+f"(c[2]), "+f"(c[3])
        : "r"(a[0]), "r"(a[1]), "r"(a[2]), "r"(a[3]), "r"(b0), "r"(b1));
}

__device__ __forceinline__ void mma_fp16(float c[4], const uint32_t a[4],
                                         uint32_t b0, uint32_t b1) {
    asm volatile(
        "mma.sync.aligned.m16n8k16.row.col.f32.f16.f16.f32 "
        "{%0,%1,%2,%3}, {%4,%5,%6,%7}, {%8,%9}, {%0,%1,%2,%3};"
        : "+f"(c[0]), "+f"(c[1]), "+f"(c[2]), "+f"(c[3])
        : "r"(a[0]), "r"(a[1]), "r"(a[2]), "r"(a[3]), "r"(b0), "r"(b1));
}

#define BK 32
#define ROWB 80
#define TILE_SB (128 * ROWB)
#define KT_N (KDIM / BK)               // 16

// =================== fp16 2-pass HMMA GEMM (P matrix) ========================
// C = (Ahi+Alo) @ Bh^T; A split fp16 (exact), B single fp16.
#define F16_STAGE (3 * TILE_SB)          // 30720
#define F16_SMEM (2 * F16_STAGE)         // 61440

__global__ __launch_bounds__(256, 2)
void gemm_fp16(const __half* __restrict__ Ahi,
               const __half* __restrict__ Alo,
               const __half* __restrict__ Bh,
               int M, int N, float* __restrict__ C, int ldc,
               const float* __restrict__ bias) {
    extern __shared__ char smem[];
    const uint32_t sb = smem_u32(smem);
    const int tid = threadIdx.x;
    const int wid = tid >> 5, lid = tid & 31;
    const int wm = wid & 3, wn = wid >> 2;
    const int nb = blockIdx.x, mb = blockIdx.y;

    const __half* __restrict__ srcs[3] = {Ahi, Alo, Bh};

    float acc[2][8][4];
#pragma unroll
    for (int i = 0; i < 2; i++)
#pragma unroll
        for (int j = 0; j < 8; j++)
#pragma unroll
            for (int q = 0; q < 4; q++) acc[i][j][q] = 0.0f;

    auto load_stage = [&](int st, int kt) {
#pragma unroll
        for (int t = 0; t < 3; t++) {
#pragma unroll
            for (int i = 0; i < 2; i++) {
                const int idx = tid + i * 256;
                const int row = idx >> 2, ch = idx & 3;
                const long long grow =
                    (t < 2) ? (long long)mb * 128 + row : (long long)nb * 128 + row;
                const bool ok = (t < 2) ? (grow < M) : (grow < N);
                const __half* src = srcs[t] + grow * KDIM + kt * BK + ch * 8;
                const uint32_t dst = sb + st * F16_STAGE + t * TILE_SB + row * ROWB + ch * 16;
                const int sz = ok ? 16 : 0;
                asm volatile("cp.async.cg.shared.global [%0], [%1], 16, %2;"
                             :: "r"(dst), "l"(src), "r"(sz) : "memory");
            }
        }
        asm volatile("cp.async.commit_group;" ::: "memory");
    };

    const int lr = lid & 15;
    const int lc = lid >> 4;

    load_stage(0, 0);

    for (int kt = 0; kt < KT_N; kt++) {
        const int st = kt & 1;
        if (kt + 1 < KT_N) {
            load_stage(st ^ 1, kt + 1);
            asm volatile("cp.async.wait_group 1;" ::: "memory");
        } else {
            asm volatile("cp.async.wait_group 0;" ::: "memory");
        }
        __syncthreads();

        const uint32_t stg = sb + st * F16_STAGE;
        const uint32_t aBaseHi = stg + 0 * TILE_SB;
        const uint32_t aBaseLo = stg + 1 * TILE_SB;
        const uint32_t bBase = stg + 2 * TILE_SB;

#pragma unroll
        for (int k16 = 0; k16 < 2; k16++) {
            const uint32_t koff = k16 * 32 + lc * 16;

            uint32_t ahi[2][4], alo[2][4];
#pragma unroll
            for (int mf = 0; mf < 2; mf++) {
                const uint32_t roff = (uint32_t)(wm * 32 + mf * 16 + lr) * ROWB + koff;
                ldm_x4(aBaseHi + roff, ahi[mf]);
                ldm_x4(aBaseLo + roff, alo[mf]);
            }
#pragma unroll
            for (int reg = 0; reg < 4; reg++) {
                const uint32_t roff = (uint32_t)(wn * 64 + reg * 16 + lr) * ROWB + koff;
                uint32_t bh[4];
                ldm_x4(bBase + roff, bh);
#pragma unroll
                for (int mf = 0; mf < 2; mf++) {
                    mma_fp16(acc[mf][reg * 2 + 0], ahi[mf], bh[0], bh[2]);
                    mma_fp16(acc[mf][reg * 2 + 0], alo[mf], bh[0], bh[2]);
                    mma_fp16(acc[mf][reg * 2 + 1], ahi[mf], bh[1], bh[3]);
                    mma_fp16(acc[mf][reg * 2 + 1], alo[mf], bh[1], bh[3]);
                }
            }
        }
        __syncthreads();
    }

    const int lr4 = lid >> 2;
    const int lc2 = (lid & 3) * 2;
#pragma unroll
    for (int mf = 0; mf < 2; mf++) {
#pragma unroll
        for (int nf = 0; nf < 8; nf++) {
            const int m = mb * 128 + wm * 32 + mf * 16 + lr4;
            const int n = nb * 128 + wn * 64 + nf * 8 + lc2;
            if (n >= N) continue;
            float b0 = 0.f, b1 = 0.f;
            if (bias) { b0 = bias[n]; b1 = bias[n + 1]; }
            if (m < M) {
                float2 v = make_float2(acc[mf][nf][0] + b0, acc[mf][nf][1] + b1);
                *reinterpret_cast<float2*>(C + (long long)m * ldc + n) = v;
            }
            if (m + 8 < M) {
                float2 v = make_float2(acc[mf][nf][2] + b0, acc[mf][nf][3] + b1);
                *reinterpret_cast<float2*>(C + (long long)(m + 8) * ldc + n) = v;
            }
        }
    }
}

// =================== fp16 SINGLE-pass HMMA GEMM (logits) =====================
// C = A16 @ B16^T + bias. 2 tiles/stage = 20KB, 2 stages, 2 CTAs/SM.
#define F161_STAGE (2 * TILE_SB)         // 20480
#define F161_SMEM (2 * F161_STAGE)       // 40960

__global__ __launch_bounds__(256, 2)
void gemm_f16_1p(const __half* __restrict__ A16,
                 const __half* __restrict__ B16,
                 int M, int N, float* __restrict__ C, int ldc,
                 const float* __restrict__ bias) {
    extern __shared__ char smem[];
    const uint32_t sb = smem_u32(smem);
    const int tid = threadIdx.x;
    const int wid = tid >> 5, lid = tid & 31;
    const int wm = wid & 3, wn = wid >> 2;
    const int nb = blockIdx.x, mb = blockIdx.y;

    float acc[2][8][4];
#pragma unroll
    for (int i = 0; i < 2; i++)
#pragma unroll
        for (int j = 0; j < 8; j++)
#pragma unroll
            for (int q = 0; q < 4; q++) acc[i][j][q] = 0.0f;

    auto load_stage = [&](int st, int kt) {
#pragma unroll
        for (int t = 0; t < 2; t++) {
#pragma unroll
            for (int i = 0; i < 2; i++) {
                const int idx = tid + i * 256;
                const int row = idx >> 2, ch = idx & 3;
                const long long grow =
                    (t == 0) ? (long long)mb * 128 + row : (long long)nb * 128 + row;
                const bool ok = (t == 0) ? (grow < M) : (grow < N);
                const __half* src = (t == 0 ? A16 : B16) + grow * KDIM + kt * BK + ch * 8;
                const uint32_t dst = sb + st * F161_STAGE + t * TILE_SB + row * ROWB + ch * 16;
                const int sz = ok ? 16 : 0;
                asm volatile("cp.async.cg.shared.global [%0], [%1], 16, %2;"
                             :: "r"(dst), "l"(src), "r"(sz) : "memory");
            }
        }
        asm volatile("cp.async.commit_group;" ::: "memory");
    };

    const int lr = lid & 15;
    const int lc = lid >> 4;

    load_stage(0, 0);

    for (int kt = 0; kt < KT_N; kt++) {
        const int st = kt & 1;
        if (kt + 1 < KT_N) {
            load_stage(st ^ 1, kt + 1);
            asm volatile("cp.async.wait_group 1;" ::: "memory");
        } else {
            asm volatile("cp.async.wait_group 0;" ::: "memory");
        }
        __syncthreads();

        const uint32_t stg = sb + st * F161_STAGE;
        const uint32_t aBase = stg;
        const uint32_t bBase = stg + TILE_SB;

#pragma unroll
        for (int k16 = 0; k16 < 2; k16++) {
            const uint32_t koff = k16 * 32 + lc * 16;

            uint32_t af[2][4];
#pragma unroll
            for (int mf = 0; mf < 2; mf++) {
                const uint32_t roff = (uint32_t)(wm * 32 + mf * 16 + lr) * ROWB + koff;
                ldm_x4(aBase + roff, af[mf]);
            }
#pragma unroll
            for (int reg = 0; reg < 4; reg++) {
                const uint32_t roff = (uint32_t)(wn * 64 + reg * 16 + lr) * ROWB + koff;
                uint32_t bh[4];
                ldm_x4(bBase + roff, bh);
#pragma unroll
                for (int mf = 0; mf < 2; mf++) {
                    mma_fp16(acc[mf][reg * 2 + 0], af[mf], bh[0], bh[2]);
                    mma_fp16(acc[mf][reg * 2 + 1], af[mf], bh[1], bh[3]);
                }
            }
        }
        __syncthreads();
    }

    const int lr4 = lid >> 2;
    const int lc2 = (lid & 3) * 2;
#pragma unroll
    for (int mf = 0; mf < 2; mf++) {
#pragma unroll
        for (int nf = 0; nf < 8; nf++) {
            const int m = mb * 128 + wm * 32 + mf * 16 + lr4;
            const int n = nb * 128 + wn * 64 + nf * 8 + lc2;
            if (n >= N) continue;
            float b0 = 0.f, b1 = 0.f;
            if (bias) { b0 = bias[n]; b1 = bias[n + 1]; }
            if (m < M) {
                float2 v = make_float2(acc[mf][nf][0] + b0, acc[mf][nf][1] + b1);
                *reinterpret_cast<float2*>(C + (long long)m * ldc + n) = v;
            }
            if (m + 8 < M) {
                float2 v = make_float2(acc[mf][nf][2] + b0, acc[mf][nf][3] + b1);
                *reinterpret_cast<float2*>(C + (long long)(m + 8) * ldc + n) = v;
            }
        }
    }
}

// =================== persistent recurrence kernel v5 (bf16 3-pass) ==========
#define RNN_CTAS 128
#define RNN_THR 256
#define WT16 16384
#define HT32 32768
#define OFF_W 0
#define OFF_H0 (6 * WT16)
#define OFF_H1 (OFF_H0 + 2 * HT32)
#define OFF_P (OFF_H1 + 2 * HT32)         // 229376: P prefetch, 32x16 fp32
#define RNN_SMEM (OFF_P + 2048)           // 231424
#define OFF_R OFF_H0
#define REDSTR 17

__global__ __launch_bounds__(RNN_THR, 1)
void rnn_persist(const int* __restrict__ inputs,
                 const float* __restrict__ W0,
                 const float* __restrict__ b0,
                 const float* __restrict__ Wl,
                 const float* __restrict__ bl,
                 float* __restrict__ hfin) {
    extern __shared__ char smc[];
    const uint32_t sbase = smem_u32(smc);
    float* const smf = reinterpret_cast<float*>(smc);
    const int tid = threadIdx.x;
    const int wid = tid >> 5, lid = tid & 31;
    const int bg = blockIdx.x >> 5;
    const int cg = blockIdx.x & 31;
    const int cbase = cg * 16;

    for (int i = tid; i < 16 * 512; i += RNN_THR) {
        const int r = i >> 9, k = i & 511;
        const int gc = cbase + r;
        const uint32_t off = r * 1024 + (((k >> 3) ^ (r & 7)) << 4) + (k & 7) * 2;
        float v[3];
        v[0] = W0[gc * 1024 + k];
        v[1] = Wl[gc * 1024 + 512 + k];
        v[2] = Wl[gc * 1024 + k];
#pragma unroll
        for (int t = 0; t < 3; t++) {
            const __nv_bfloat16 hi = __float2bfloat16(v[t]);
            const __nv_bfloat16 lo = __float2bfloat16(v[t] - __bfloat162float(hi));
            char* base = smc + OFF_W + (2 * t) * WT16 + off;
            *reinterpret_cast<__nv_bfloat16*>(base) = hi;
            *reinterpret_cast<__nv_bfloat16*>(base + WT16) = lo;
        }
    }
    __syncthreads();

    const int mw = wid & 1;
    const int kw = wid >> 1;
    const int lr = lid & 15, lc = lid >> 4;

    const int ecoll = tid & 15, erow = tid >> 4;
    const int ecol = cbase + ecoll;
    const float b0c = b0[ecol], blc = bl[ecol];

    const int arow = mw * 16 + lr;
    const uint32_t aRowH0 = sbase + OFF_H0 + arow * 1024;
    const uint32_t aRowH1 = sbase + OFF_H1 + arow * 1024;
    const uint32_t bRow = sbase + OFF_W + lr * 1024;
    const int axor = arow & 7;
    const int bxor = lr & 7;
    const int c0 = kw * 16 + lc;

    unsigned int* const gbar = &g_sync4[bg * 32];

    auto stage_h = [&](uint32_t offBase, const __nv_bfloat16* hi,
                       const __nv_bfloat16* lo) {
#pragma unroll
        for (int j = 0; j < 16; j++) {
            const int idx = tid + j * 256;
            const int tile = idx >> 11;
            const int c = idx & 2047;
            const int row = c >> 6, ch = c & 63;
            const __nv_bfloat16* src =
                (tile ? lo : hi) + (long long)(bg * 32 + row) * HH + ch * 8;
            const uint32_t dst = sbase + offBase + tile * HT32 + row * 1024 +
                                 ((ch ^ (row & 7)) << 4);
            asm volatile("cp.async.cg.shared.global [%0], [%1], 16;"
                         :: "r"(dst), "l"(src) : "memory");
        }
        asm volatile("cp.async.commit_group;" ::: "memory");
    };

    for (int p = 0; p <= SS; p++) {
        float acc0[2][4] = {{0, 0, 0, 0}, {0, 0, 0, 0}};
        float acc1[2][4] = {{0, 0, 0, 0}, {0, 0, 0, 0}};

        if (p < SS && tid < 128) {
            const int row = tid >> 2, ch = tid & 3;
            const int tok = __ldg(inputs + p * BB + bg * 32 + row);
            const float* src = g_P + (long long)tok * HH + cbase + ch * 4;
            const uint32_t dst = sbase + OFF_P + row * 64 + ch * 16;
            asm volatile("cp.async.cg.shared.global [%0], [%1], 16;"
                         :: "r"(dst), "l"(src) : "memory");
        }
        stage_h(OFF_H0, g_h0bh[(p + 1) & 1], g_h0bl[(p + 1) & 1]);
        stage_h(OFF_H1, g_h1bh[p & 1], g_h1bl[p & 1]);
        asm volatile("cp.async.wait_group 1;" ::: "memory");
        __syncthreads();

        // ---- pass A: h0 x W0h -> acc0 ; h0 x Wlx -> acc1 ----
#pragma unroll
        for (int i = 0; i < 8; i++) {
            const uint32_t sc = (uint32_t)((c0 + i * 2) ^ axor) << 4;
            const uint32_t wc = (uint32_t)((c0 + i * 2) ^ bxor) << 4;
            uint32_t ah[4], al[4], b0h[4], b0l[4], bxh[4], bxl[4];
            ldm_x4(aRowH0 + sc, ah);
            ldm_x4(aRowH0 + HT32 + sc, al);
            ldm_x4(bRow + 0 * WT16 + wc, b0h);
            ldm_x4(bRow + 1 * WT16 + wc, b0l);
            ldm_x4(bRow + 2 * WT16 + wc, bxh);
            ldm_x4(bRow + 3 * WT16 + wc, bxl);
            mma_bf16(acc0[0], ah, b0h[0], b0h[2]);
            mma_bf16(acc0[1], ah, b0h[1], b0h[3]);
            mma_bf16(acc0[0], ah, b0l[0], b0l[2]);
            mma_bf16(acc0[1], ah, b0l[1], b0l[3]);
            mma_bf16(acc0[0], al, b0h[0], b0h[2]);
            mma_bf16(acc0[1], al, b0h[1], b0h[3]);
            mma_bf16(acc1[0], ah, bxh[0], bxh[2]);
            mma_bf16(acc1[1], ah, bxh[1], bxh[3]);
            mma_bf16(acc1[0], ah, bxl[0], bxl[2]);
            mma_bf16(acc1[1], ah, bxl[1], bxl[3]);
            mma_bf16(acc1[0], al, bxh[0], bxh[2]);
            mma_bf16(acc1[1], al, bxh[1], bxh[3]);
        }

        asm volatile("cp.async.wait_group 0;" ::: "memory");
        __syncthreads();

        // ---- pass B: h1 x Wlh -> acc1 ----
#pragma unroll
        for (int i = 0; i < 8; i++) {
            const uint32_t sc = (uint32_t)((c0 + i * 2) ^ axor) << 4;
            const uint32_t wc = (uint32_t)((c0 + i * 2) ^ bxor) << 4;
            uint32_t ah[4], al[4], bhh[4], bhl[4];
            ldm_x4(aRowH1 + sc, ah);
            ldm_x4(aRowH1 + HT32 + sc, al);
            ldm_x4(bRow + 4 * WT16 + wc, bhh);
            ldm_x4(bRow + 5 * WT16 + wc, bhl);
            mma_bf16(acc1[0], ah, bhh[0], bhh[2]);
            mma_bf16(acc1[1], ah, bhh[1], bhh[3]);
            mma_bf16(acc1[0], ah, bhl[0], bhl[2]);
            mma_bf16(acc1[1], ah, bhl[1], bhl[3]);
            mma_bf16(acc1[0], al, bhh[0], bhh[2]);
            mma_bf16(acc1[1], al, bhh[1], bhh[3]);
        }

        // ---- write k-slice frags to red (aliases h0 buffer) ----
        {
            const int rg = lid >> 2, cc = (lid & 3) * 2;
            float* red = smf + OFF_R / 4;
            const int m = mw * 16 + rg;
#pragma unroll
            for (int nf = 0; nf < 2; nf++) {
                const int n = nf * 8 + cc;
                float* r0 = red + ((0 * 4 + kw) * 32 + m) * REDSTR + n;
                float* r1 = red + ((1 * 4 + kw) * 32 + m) * REDSTR + n;
                r0[0] = acc0[nf][0]; r0[1] = acc0[nf][1];
                r0[8 * REDSTR] = acc0[nf][2]; r0[8 * REDSTR + 1] = acc0[nf][3];
                r1[0] = acc1[nf][0]; r1[1] = acc1[nf][1];
                r1[8 * REDSTR] = acc1[nf][2]; r1[8 * REDSTR + 1] = acc1[nf][3];
            }
        }
        __syncthreads();

        // ---- epilogue ----
        __half t16s[2];
        {
            float* red = smf + OFF_R / 4;
            const float* smP = smf + OFF_P / 4;
#pragma unroll
            for (int e = 0; e < 2; e++) {
                const int row = erow + e * 16;
                const int gbr = bg * 32 + row;
                float s0 = 0.f, s1 = 0.f;
#pragma unroll
                for (int q = 0; q < 4; q++) {
                    s0 += red[((0 * 4 + q) * 32 + row) * REDSTR + ecoll];
                    s1 += red[((1 * 4 + q) * 32 + row) * REDSTR + ecoll];
                }
                const long long o = (long long)gbr * HH + ecol;
                if (p < SS) {
                    const float v = tanhf(s0 + smP[row * 16 + ecoll] + b0c);
                    const __nv_bfloat16 hv = __float2bfloat16(v);
                    const __nv_bfloat16 lv = __float2bfloat16(v - __bfloat162float(hv));
                    g_h0bh[p & 1][o] = hv;
                    g_h0bl[p & 1][o] = lv;
                    if (p == SS - 1) hfin[o] = v;
                }
                if (p >= 1) {
                    const float v = tanhf(s1 + blc);
                    const __nv_bfloat16 hv = __float2bfloat16(v);
                    const __nv_bfloat16 lv = __float2bfloat16(v - __bfloat162float(hv));
                    g_h1bh[(p + 1) & 1][o] = hv;
                    g_h1bl[(p + 1) & 1][o] = lv;
                    t16s[e] = __float2half(v);
                    if (p == SS) hfin[BB * HH + o] = v;
                }
            }
        }

        if (p < SS) {
            __syncthreads();
            if (tid == 0) {
                asm volatile("red.release.gpu.global.add.u32 [%0], 1;"
                             :: "l"(gbar) : "memory");
            }
        }

        if (p >= 1) {
            const int s = p - 1;
#pragma unroll
            for (int e = 0; e < 2; e++) {
                const int gbr = bg * 32 + erow + e * 16;
                const long long ot = ((long long)s * BB + gbr) * HH + ecol;
                g_T16[ot] = t16s[e];
            }
        }

        if (p < SS) {
            if (tid == 0) {
                const unsigned int target = (unsigned)(p + 1) * 32;
                unsigned int v;
                do {
                    asm volatile("ld.acquire.gpu.global.u32 %0, [%1];"
                                 : "=r"(v) : "l"(gbar) : "memory");
                } while (v < target);
            }
            __syncthreads();
        }
    }
}

// ---------------- prep kernels -----------------------------------------------
__global__ void prep_w0x_f16(const float* __restrict__ W0) {
    int idx = blockIdx.x * blockDim.x + threadIdx.x;
    if (idx >= HH * EE) return;
    int c = idx / EE;
    int e = idx % EE;
    g_X16[c * EE + e] = __float2half(W0[c * (HH + EE) + HH + e]);
}

__global__ void split_emb_f16(const float* __restrict__ src, float scale) {
    int i = blockIdx.x * blockDim.x + threadIdx.x;
    if (i >= VV * EE) return;
    float v = src[i] * scale;
    __half h = __float2half(v);
    g_E16h[i] = h;
    g_E16l[i] = __float2half(v - __half2float(h));
}

__global__ void conv_fp16(const float* __restrict__ src, __half* __restrict__ dst,
                          int n) {
    int i = blockIdx.x * blockDim.x + threadIdx.x;
    if (i < n) dst[i] = __float2half(src[i]);
}

__global__ void init_state(const float* __restrict__ hidden) {
    int i = blockIdx.x * blockDim.x + threadIdx.x;
    if (i < 128) g_sync4[i] = 0;
    if (i < BB * HH) {
        float v0 = hidden[i];
        __nv_bfloat16 h0 = __float2bfloat16(v0);
        g_h0bh[1][i] = h0;
        g_h0bl[1][i] = __float2bfloat16(v0 - __bfloat162float(h0));
        float v1 = hidden[BB * HH + i];
        __nv_bfloat16 h1 = __float2bfloat16(v1);
        g_h1bh[1][i] = h1;
        g_h1bl[1][i] = __float2bfloat16(v1 - __bfloat162float(h1));
    }
}

// ---------------- launch ------------------------------------------------------
extern "C" void kernel_launch(void* const* d_in, const int* in_sizes, int n_in,
                              void* d_out, int out_size) {
    const int*   inputs = (const int*)  d_in[0];
    const float* hidden = (const float*)d_in[1];
    const float* emb    = (const float*)d_in[2];
    const float* W0     = (const float*)d_in[3];
    const float* b0     = (const float*)d_in[4];
    const float* Wl     = (const float*)d_in[5];
    const float* bl     = (const float*)d_in[6];
    const float* Wout   = (const float*)d_in[7];
    const float* bout   = (const float*)d_in[8];

    float* logits = (float*)d_out;
    float* hfin   = (float*)d_out + (long long)SS * BB * VV;

    cudaFuncSetAttribute(gemm_fp16, cudaFuncAttributeMaxDynamicSharedMemorySize,
                         F16_SMEM);
    cudaFuncSetAttribute(gemm_f16_1p, cudaFuncAttributeMaxDynamicSharedMemorySize,
                         F161_SMEM);
    cudaFuncSetAttribute(rnn_persist, cudaFuncAttributeMaxDynamicSharedMemorySize,
                         RNN_SMEM);

    float* pP = nullptr;
    cudaGetSymbolAddress((void**)&pP, g_P);
    __half *pT16, *pW16, *pEh, *pEl, *pX16;
    cudaGetSymbolAddress((void**)&pT16, g_T16);
    cudaGetSymbolAddress((void**)&pW16, g_W16);
    cudaGetSymbolAddress((void**)&pEh, g_E16h);
    cudaGetSymbolAddress((void**)&pEl, g_E16l);
    cudaGetSymbolAddress((void**)&pX16, g_X16);

    const float scale = 22.62741699796952f;  // sqrt(512)

    // 1. prep
    init_state<<<(BB * HH + 255) / 256, 256>>>(hidden);
    prep_w0x_f16<<<(HH * EE + 255) / 256, 256>>>(W0);
    split_emb_f16<<<(VV * EE + 255) / 256, 256>>>(emb, scale);
    conv_fp16<<<(VV * HH + 255) / 256, 256>>>(Wout, pW16, VV * HH);

    // 2. P = scale*emb @ W0x^T  (M=10000, N=512, K=512) — fp16 2-pass
    {
        dim3 grid((HH + 127) / 128, (VV + 127) / 128);
        gemm_fp16<<<grid, 256, F16_SMEM>>>(pEh, pEl, pX16,
                                           VV, HH, pP, HH, nullptr);
    }

    // 3. full recurrence in ONE persistent kernel (bf16 3-pass, unchanged)
    rnn_persist<<<RNN_CTAS, RNN_THR, RNN_SMEM>>>(inputs, W0, b0, Wl, bl, hfin);

    // 4. logits = tops @ Wout^T + bout  — fp16 SINGLE-pass
    {
        dim3 grid((VV + 127) / 128, (SS * BB + 127) / 128);
        gemm_f16_1p<<<grid, 256, F161_SMEM>>>(pT16, pW16,
                                              SS * BB, VV, logits, VV, bout);
    }
}